// round 2
// baseline (speedup 1.0000x reference)
#include <cuda_runtime.h>
#include <math.h>

#define NN   20000
#define EE   320000
#define BBATCH 128
#define FIN  25
#define DIM  64
#define NH   8
#define F512 512   // NH*DIM

// ---------------- scratch (static device globals; no allocation) ----------------
__device__ float g_h0[NN * DIM];
__device__ float g_xh[NN * F512];
__device__ float g_as[NN * NH];
__device__ float g_ad[NN * NH];
__device__ int   g_cnt[NN];
__device__ int   g_offs[NN + 1];
__device__ int   g_cursor[NN];
__device__ int   g_csr[EE];
__device__ float g_agg[NN * F512];
__device__ float g_out[NN * DIM];

__device__ __forceinline__ float lrelu(float x) { return x > 0.f ? x : 0.2f * x; }
__device__ __forceinline__ float sigmoidf_(float x) { return 1.f / (1.f + __expf(-x)); }

// ---------------- k1: h0 = relu(x @ W0 + b0) ----------------
// block = 256 threads = 4 rows x 64 cols
__global__ void k_h0(const float* __restrict__ x, const float* __restrict__ W0,
                     const float* __restrict__ b0) {
    __shared__ float sW[FIN * DIM];
    __shared__ float sb[DIM];
    __shared__ float sx[4][FIN];
    int tid = threadIdx.x;
    for (int i = tid; i < FIN * DIM; i += 256) sW[i] = W0[i];
    if (tid < DIM) sb[tid] = b0[tid];
    int rb = blockIdx.x * 4;
    if (tid < 4 * FIN) sx[tid / FIN][tid % FIN] = x[rb * FIN + tid];
    __syncthreads();
    int c = tid & 63, r = tid >> 6;
    float acc = sb[c];
#pragma unroll
    for (int k = 0; k < FIN; k++) acc = fmaf(sx[r][k], sW[k * DIM + c], acc);
    g_h0[(rb + r) * DIM + c] = fmaxf(acc, 0.f);
}

// ---------------- k2: xh = h0 @ Wg  (N x 64 @ 64 x 512) ----------------
// block: 256 threads, 32 rows x 512 cols.  thread tile 8x8 (cols strided by 64,
// so col j of a thread == head j, channel tc)
__global__ void __launch_bounds__(256) k_xh(const float* __restrict__ Wg) {
    __shared__ float h0s[32][65];
    int tid = threadIdx.x;
    int rb = blockIdx.x * 32;
    for (int idx = tid; idx < 32 * DIM; idx += 256)
        h0s[idx >> 6][idx & 63] = g_h0[rb * DIM + idx];
    __syncthreads();
    int tc = tid & 63, tr = tid >> 6;
    float acc[8][8];
#pragma unroll
    for (int i = 0; i < 8; i++)
#pragma unroll
        for (int j = 0; j < 8; j++) acc[i][j] = 0.f;
#pragma unroll 4
    for (int k = 0; k < DIM; k++) {
        float wv[8];
#pragma unroll
        for (int j = 0; j < 8; j++) wv[j] = __ldg(&Wg[k * F512 + tc + 64 * j]);
#pragma unroll
        for (int i = 0; i < 8; i++) {
            float hv = h0s[tr * 8 + i][k];
#pragma unroll
            for (int j = 0; j < 8; j++) acc[i][j] = fmaf(hv, wv[j], acc[i][j]);
        }
    }
#pragma unroll
    for (int i = 0; i < 8; i++) {
        size_t row = (size_t)(rb + tr * 8 + i) * F512;
#pragma unroll
        for (int j = 0; j < 8; j++) g_xh[row + tc + 64 * j] = acc[i][j];
    }
}

// ---------------- k2b: a_s[n,h], a_d[n,h] = dot(xh[n,h,:], att_{src,dst}[h,:]) ----
// warp per (n,h)
__global__ void k_att(const float* __restrict__ att_src, const float* __restrict__ att_dst) {
    int gw = (blockIdx.x * blockDim.x + threadIdx.x) >> 5;
    int lane = threadIdx.x & 31;
    int n = gw >> 3, h = gw & 7;
    const float* row = g_xh + (size_t)n * F512 + h * 64;
    float a = row[lane], b = row[lane + 32];
    float s1 = a * att_src[h * 64 + lane] + b * att_src[h * 64 + lane + 32];
    float s2 = a * att_dst[h * 64 + lane] + b * att_dst[h * 64 + lane + 32];
#pragma unroll
    for (int o = 16; o; o >>= 1) {
        s1 += __shfl_xor_sync(0xffffffffu, s1, o);
        s2 += __shfl_xor_sync(0xffffffffu, s2, o);
    }
    if (lane == 0) { g_as[n * 8 + h] = s1; g_ad[n * 8 + h] = s2; }
}

// ---------------- CSR build ----------------
__global__ void k_zero() {
    int i = blockIdx.x * 256 + threadIdx.x;
    if (i < NN) g_cnt[i] = 0;
}
__global__ void k_hist(const int* __restrict__ ei) {
    int e = blockIdx.x * 256 + threadIdx.x;
    if (e < EE) atomicAdd(&g_cnt[ei[EE + e]], 1);
}
__global__ void k_scan() {  // 1 block, 1024 threads
    __shared__ int partials[1024];
    int t = threadIdx.x;
    const int CH = 20;  // 1024*20 = 20480 >= NN
    int base = t * CH;
    int local[CH];
    int s = 0;
#pragma unroll
    for (int u = 0; u < CH; u++) {
        int idx = base + u;
        int v = (idx < NN) ? g_cnt[idx] : 0;
        local[u] = s;
        s += v;
    }
    partials[t] = s;
    __syncthreads();
    for (int o = 1; o < 1024; o <<= 1) {
        int v = (t >= o) ? partials[t - o] : 0;
        __syncthreads();
        partials[t] += v;
        __syncthreads();
    }
    int pre = (t > 0) ? partials[t - 1] : 0;
#pragma unroll
    for (int u = 0; u < CH; u++) {
        int idx = base + u;
        if (idx < NN) {
            int o = pre + local[u];
            g_offs[idx] = o;
            g_cursor[idx] = o;
        }
    }
    if (t == 1023) g_offs[NN] = partials[1023];
}
__global__ void k_scatter(const int* __restrict__ ei) {
    int e = blockIdx.x * 256 + threadIdx.x;
    if (e < EE) {
        int d = ei[EE + e];
        int p = atomicAdd(&g_cursor[d], 1);
        g_csr[p] = ei[e];
    }
}

// ---------------- k4: GAT aggregation, warp per dst node ----------------
// pass1: per-head max of leaky_relu(a_s[src]+a_d[n]) (4 edges x 8 heads per iter)
// pass2: w = exp(e - m); acc += w * xh[src]; then agg = relu(acc/sum + bg)
__global__ void __launch_bounds__(256) k_agg(const float* __restrict__ bg) {
    int n = (blockIdx.x * blockDim.x + threadIdx.x) >> 5;
    int lane = threadIdx.x & 31;
    if (n >= NN) return;
    int s0 = g_offs[n], s1 = g_offs[n + 1];
    int hh = lane & 7;
    float adh = g_ad[n * 8 + hh];

    // ---- pass 1: max ----
    float m = -INFINITY;
    if (lane < 8) m = lrelu(g_as[n * 8 + lane] + adh);  // self-loop
    for (int i = s0 + (lane >> 3); i < s1; i += 4) {
        int src = g_csr[i];
        float e = lrelu(g_as[src * 8 + hh] + adh);
        m = fmaxf(m, e);
    }
    m = fmaxf(m, __shfl_xor_sync(0xffffffffu, m, 8));
    m = fmaxf(m, __shfl_xor_sync(0xffffffffu, m, 16));
    // lane l now holds max for head (l&7); lanes 0..7 hold m[h]

    // ---- pass 2: weighted accumulate ----
    float4 acc[4];
#pragma unroll
    for (int j = 0; j < 4; j++) acc[j] = make_float4(0.f, 0.f, 0.f, 0.f);
    float ssum = 0.f;
    for (int i = s0 - 1; i < s1; ++i) {
        int src = (i < s0) ? n : g_csr[i];
        float w = 0.f;
        if (lane < 8) {
            float e = lrelu(g_as[src * 8 + lane] + adh);
            w = __expf(e - m);
            ssum += w;
        }
        const float4* row = (const float4*)(g_xh + (size_t)src * F512);
#pragma unroll
        for (int j = 0; j < 4; j++) {
            int f = lane + 32 * j;
            float wj = __shfl_sync(0xffffffffu, w, f >> 4);
            float4 v = row[f];
            acc[j].x = fmaf(wj, v.x, acc[j].x);
            acc[j].y = fmaf(wj, v.y, acc[j].y);
            acc[j].z = fmaf(wj, v.z, acc[j].z);
            acc[j].w = fmaf(wj, v.w, acc[j].w);
        }
    }
    float4* orow = (float4*)(g_agg + (size_t)n * F512);
#pragma unroll
    for (int j = 0; j < 4; j++) {
        int f = lane + 32 * j;
        float sj = __shfl_sync(0xffffffffu, ssum, f >> 4);
        float inv = 1.0f / sj;
        int ch = 4 * f;
        float4 o;
        o.x = fmaxf(acc[j].x * inv + __ldg(&bg[ch + 0]), 0.f);
        o.y = fmaxf(acc[j].y * inv + __ldg(&bg[ch + 1]), 0.f);
        o.z = fmaxf(acc[j].z * inv + __ldg(&bg[ch + 2]), 0.f);
        o.w = fmaxf(acc[j].w * inv + __ldg(&bg[ch + 3]), 0.f);
        orow[f] = o;
    }
}

// ---------------- k5: out = relu(agg @ Wh + bh)  (N x 512 @ 512 x 64) ----------
// BM=128, BK=32, BN=64; 256 threads; thread tile 8 rows x 4 cols
__global__ void __launch_bounds__(256) k_out(const float* __restrict__ Wh,
                                             const float* __restrict__ bh) {
    __shared__ float As[128][33];
    __shared__ float Bs[32][68];
    int tid = threadIdx.x;
    int rb = blockIdx.x * 128;
    int c0 = (tid & 15) * 4, r0 = (tid >> 4) * 8;
    float acc[8][4];
#pragma unroll
    for (int i = 0; i < 8; i++)
#pragma unroll
        for (int j = 0; j < 4; j++) acc[i][j] = 0.f;
    for (int kc = 0; kc < F512; kc += 32) {
        for (int idx = tid; idx < 128 * 32; idx += 256) {
            int r = idx >> 5, k = idx & 31;
            int row = rb + r;
            As[r][k] = (row < NN) ? g_agg[(size_t)row * F512 + kc + k] : 0.f;
        }
        for (int idx = tid; idx < 32 * 64; idx += 256) {
            int k = idx >> 6, c = idx & 63;
            Bs[k][c] = Wh[(kc + k) * 64 + c];
        }
        __syncthreads();
#pragma unroll 8
        for (int k = 0; k < 32; k++) {
            float4 bv = *(const float4*)&Bs[k][c0];
#pragma unroll
            for (int i = 0; i < 8; i++) {
                float av = As[r0 + i][k];
                acc[i][0] = fmaf(av, bv.x, acc[i][0]);
                acc[i][1] = fmaf(av, bv.y, acc[i][1]);
                acc[i][2] = fmaf(av, bv.z, acc[i][2]);
                acc[i][3] = fmaf(av, bv.w, acc[i][3]);
            }
        }
        __syncthreads();
    }
    float4 bh4 = *(const float4*)&bh[c0];
#pragma unroll
    for (int i = 0; i < 8; i++) {
        int row = rb + r0 + i;
        if (row < NN) {
            float4 o;
            o.x = fmaxf(acc[i][0] + bh4.x, 0.f);
            o.y = fmaxf(acc[i][1] + bh4.y, 0.f);
            o.z = fmaxf(acc[i][2] + bh4.z, 0.f);
            o.w = fmaxf(acc[i][3] + bh4.w, 0.f);
            *(float4*)&g_out[(size_t)row * 64 + c0] = o;
        }
    }
}

// ---------------- k6: Set2Set (3 steps) + final MLP; one block per graph -------
__global__ void __launch_bounds__(256) k_s2s(
    const int* __restrict__ batch, const float* __restrict__ W_ih,
    const float* __restrict__ W_hh, const float* __restrict__ b_ih,
    const float* __restrict__ b_hh, const float* __restrict__ W1,
    const float* __restrict__ b1, const float* __restrict__ W2,
    const float* __restrict__ b2, float* __restrict__ y) {
    int b = blockIdx.x;
    int tid = threadIdx.x, lane = tid & 31, wid = tid >> 5;
    __shared__ float qs[128], hhv[64], ccv[64], gg[256];
    __shared__ float red[8][64];
    __shared__ float sred[8], mw[8];
    __shared__ float mfin_s;
    __shared__ int seg[2];
    if (tid == 0) {
        int lo = 0, hi = NN;
        while (lo < hi) { int mid = (lo + hi) >> 1; if (batch[mid] < b) lo = mid + 1; else hi = mid; }
        seg[0] = lo;
        hi = NN;
        while (lo < hi) { int mid = (lo + hi) >> 1; if (batch[mid] < b + 1) lo = mid + 1; else hi = mid; }
        seg[1] = lo;
    }
    if (tid < 128) qs[tid] = 0.f;
    if (tid < 64) { hhv[tid] = 0.f; ccv[tid] = 0.f; }
    __syncthreads();
    int s0 = seg[0], s1 = seg[1];

    for (int it = 0; it < 3; ++it) {
        // LSTM cell (per-graph row)
        float g = b_ih[tid] + b_hh[tid];
        const float* wi = W_ih + tid * 128;
#pragma unroll 4
        for (int k = 0; k < 128; k++) g = fmaf(qs[k], wi[k], g);
        const float* wh = W_hh + tid * 64;
#pragma unroll 4
        for (int k = 0; k < 64; k++) g = fmaf(hhv[k], wh[k], g);
        gg[tid] = g;
        __syncthreads();
        if (tid < 64) {
            float ig = gg[tid], fg = gg[64 + tid], gv = gg[128 + tid], og = gg[192 + tid];
            float c = sigmoidf_(fg) * ccv[tid] + sigmoidf_(ig) * tanhf(gv);
            ccv[tid] = c;
            hhv[tid] = sigmoidf_(og) * tanhf(c);
        }
        __syncthreads();

        // attention over this graph's nodes, q = hhv
        float q0 = hhv[lane], q1 = hhv[lane + 32];
        float wmax = -INFINITY;
        for (int i = s0 + wid; i < s1; i += 8) {
            const float* o = g_out + (size_t)i * 64;
            float v = o[lane] * q0 + o[lane + 32] * q1;
#pragma unroll
            for (int off = 16; off; off >>= 1) v += __shfl_xor_sync(0xffffffffu, v, off);
            wmax = fmaxf(wmax, v);
        }
        if (lane == 0) mw[wid] = wmax;
        __syncthreads();
        if (tid == 0) {
            float m = -INFINITY;
#pragma unroll
            for (int w = 0; w < 8; w++) m = fmaxf(m, mw[w]);
            mfin_s = m;
        }
        __syncthreads();
        float m = mfin_s;
        float r0a = 0.f, r1a = 0.f, sl = 0.f;
        for (int i = s0 + wid; i < s1; i += 8) {
            const float* o = g_out + (size_t)i * 64;
            float a0 = o[lane], a1 = o[lane + 32];
            float v = a0 * q0 + a1 * q1;
#pragma unroll
            for (int off = 16; off; off >>= 1) v += __shfl_xor_sync(0xffffffffu, v, off);
            float w = __expf(v - m);
            sl += w;
            r0a = fmaf(w, a0, r0a);
            r1a = fmaf(w, a1, r1a);
        }
        red[wid][lane] = r0a;
        red[wid][lane + 32] = r1a;
        if (lane == 0) sred[wid] = sl;
        __syncthreads();
        if (tid < 64) {
            float s = 0.f, r = 0.f;
#pragma unroll
            for (int w = 0; w < 8; w++) { s += sred[w]; r += red[w][tid]; }
            float inv = (s > 0.f) ? 1.0f / s : 0.f;
            qs[tid] = hhv[tid];
            qs[64 + tid] = r * inv;
        }
        __syncthreads();
    }

    // final MLP: y = relu(q_star @ W1 + b1) @ W2 + b2
    if (tid < 64) {
        float z = b1[tid];
#pragma unroll 4
        for (int k = 0; k < 128; k++) z = fmaf(qs[k], W1[k * 64 + tid], z);
        gg[tid] = fmaxf(z, 0.f);
    }
    __syncthreads();
    if (tid < 32) {
        float p = gg[tid] * W2[tid] + gg[tid + 32] * W2[tid + 32];
#pragma unroll
        for (int off = 16; off; off >>= 1) p += __shfl_xor_sync(0xffffffffu, p, off);
        if (tid == 0) y[b] = p + b2[0];
    }
}

// ---------------- launch ----------------
extern "C" void kernel_launch(void* const* d_in, const int* in_sizes, int n_in,
                              void* d_out, int out_size) {
    const float* x       = (const float*)d_in[0];
    const int*   ei      = (const int*)d_in[1];   // [2,E] int32 (JAX x64 disabled)
    const int*   batch   = (const int*)d_in[2];
    const float* W0      = (const float*)d_in[3];
    const float* b0      = (const float*)d_in[4];
    const float* Wg      = (const float*)d_in[5];
    const float* att_src = (const float*)d_in[6];
    const float* att_dst = (const float*)d_in[7];
    const float* bg      = (const float*)d_in[8];
    const float* Wh      = (const float*)d_in[9];
    const float* bh      = (const float*)d_in[10];
    const float* W_ih    = (const float*)d_in[11];
    const float* W_hh    = (const float*)d_in[12];
    const float* b_ih    = (const float*)d_in[13];
    const float* b_hh    = (const float*)d_in[14];
    const float* W1      = (const float*)d_in[15];
    const float* b1      = (const float*)d_in[16];
    const float* W2      = (const float*)d_in[17];
    const float* b2      = (const float*)d_in[18];
    float* y = (float*)d_out;

    k_h0<<<NN / 4, 256>>>(x, W0, b0);
    k_xh<<<NN / 32, 256>>>(Wg);
    k_att<<<NN * NH / 8, 256>>>(att_src, att_dst);
    k_zero<<<(NN + 255) / 256, 256>>>();
    k_hist<<<(EE + 255) / 256, 256>>>(ei);
    k_scan<<<1, 1024>>>();
    k_scatter<<<(EE + 255) / 256, 256>>>(ei);
    k_agg<<<NN / 8, 256>>>(bg);
    k_out<<<(NN + 127) / 128, 256>>>(Wh, bh);
    k_s2s<<<BBATCH, 256>>>(batch, W_ih, W_hh, b_ih, b_hh, W1, b1, W2, b2, y);
}